// round 14
// baseline (speedup 1.0000x reference)
#include <cuda_runtime.h>
#include <math.h>
#include <stdint.h>

// ---------------- problem constants ----------------
#define BB    256
#define TT    512
#define SS    8
#define CD1   5        // CD+1
#define RNN_  512
#define HH    520      // RNN + S
#define H4    2080
#define EE    1024
#define DD    1040

// ---------------- LSTM partitioning (exact, no padding) ----------------
#define G       4      // batch groups, 64 sorted batches each
#define MB      64     // batches per group
#define WHCOL   256    // width of transposed h buffer (= BB)
#define NCH     65     // h-chunks (CTAs per group); 65*8 = 520 exactly
#define CHJ     8      // h indices per chunk (4 warps x 2 jj)
#define NCOL    32     // 4*CHJ gate columns per CTA
#define KTILE   65     // K tile rows; 8 phases cover 520
#define NPH     8
#define THREADS 128    // 4 warps

// ---------------- scratch (static __device__, no allocation) ----------------
__device__ __align__(16) float g_t1[BB * EE];
__device__ __align__(16) float g_t2[BB * EE];
__device__ __align__(16) float g_h0[BB * RNN_];
__device__ __align__(16) float g_hbuf[2][HH * WHCOL];
__device__ __align__(16) float g_last[BB * HH];
__device__ __align__(16) float g_z1[BB * DD];
__device__ __align__(16) float g_z2[BB * DD];
__device__ int g_perm[BB];
// per-group barrier state, each word on its OWN 128B L2 line
__device__ __align__(128) unsigned int g_barx[G][32];
__device__ __align__(128) unsigned int g_gox[G][32];

// ---------------- helpers ----------------
__device__ __forceinline__ float fsig(float x) {
    return 1.f / (1.f + __expf(-x));
}
__device__ __forceinline__ float ftanh_(float x) {
    float ax = fabsf(x);
    float e = __expf(-2.f * ax);
    float r = (1.f - e) / (1.f + e);
    return x < 0.f ? -r : r;
}
__device__ __forceinline__ unsigned long long splat2(float w) {
    unsigned long long r;
    asm("mov.b64 %0, {%1, %1};" : "=l"(r) : "f"(w));
    return r;
}
__device__ __forceinline__ void unpk2(unsigned long long v, float& lo, float& hi) {
    asm("mov.b64 {%0, %1}, %2;" : "=f"(lo), "=f"(hi) : "l"(v));
}
#define FMA2(d, a, b) asm("fma.rn.f32x2 %0, %1, %2, %0;" : "+l"(d) : "l"(a), "l"(b))

__device__ __forceinline__ void cp16(uint32_t saddr, const void* gaddr) {
    asm volatile("cp.async.cg.shared.global [%0], [%1], 16;"
                 :: "r"(saddr), "l"(gaddr));
}

// ---------------- pairing-aware bid -> (group, chunk) map ----------------
// Wave-1 placement puts bid i and bid i+148 on the same SM (LUT[bid % 148]).
// Longest group (0) solo or paired with shortest (3); 1 with 3/2; 2 with 2.
__device__ __forceinline__ void bid_map(int bid, int& grp, int& chunk) {
    if (bid < 29)        { grp = 0; chunk = bid; }              // paired w/ 148..176 (g3)
    else if (bid < 65)   { grp = 1; chunk = bid - 29; }         // paired w/ 177..212 (g3)
    else if (bid < 94)   { grp = 1; chunk = bid - 65 + 36; }    // paired w/ 213..241 (g2)
    else if (bid < 112)  { grp = 2; chunk = bid - 94 + 29; }    // paired w/ 242..259 (g2)
    else if (bid < 148)  { grp = 0; chunk = bid - 112 + 29; }   // SOLO (no bid+148)
    else if (bid < 177)  { grp = 3; chunk = bid - 148; }
    else if (bid < 213)  { grp = 3; chunk = bid - 177 + 29; }
    else if (bid < 242)  { grp = 2; chunk = bid - 213; }
    else                 { grp = 2; chunk = bid - 242 + 47; }
}

// ---------------- GEMM: C = act(A[MxK] @ B[KxN] + bias), 32x64 tiles ----------------
__global__ void gemm_bias_act(const float* __restrict__ A, const float* __restrict__ Bw,
                              const float* __restrict__ bias, float* __restrict__ C,
                              int M, int N, int K, int act)
{
    __shared__ float sA[16][36];   // [k][m]
    __shared__ float sB[16][68];   // [k][n]; 68-float row stride stays 16B aligned
    int tid = threadIdx.x;         // 256
    int row0 = blockIdx.y * 32, col0 = blockIdx.x * 64;
    int tx = tid & 15, ty = tid >> 4;   // tx: col quad, ty: row pair
    float acc[2][4] = {{0.f, 0.f, 0.f, 0.f}, {0.f, 0.f, 0.f, 0.f}};

    for (int k0 = 0; k0 < K; k0 += 16) {
        #pragma unroll
        for (int e = 0; e < 2; ++e) {
            int idx = tid + e * 256;
            int m = idx >> 4, kk = idx & 15;
            int gr = row0 + m, gk = k0 + kk;
            sA[kk][m] = (gr < M && gk < K) ? A[(size_t)gr * K + gk] : 0.f;
        }
        {
            int r = tid >> 4, c = (tid & 15) * 4;
            int gk = k0 + r, gc = col0 + c;
            float4 v = make_float4(0.f, 0.f, 0.f, 0.f);
            if (gk < K) {
                if (gc + 3 < N) v = *(const float4*)&Bw[(size_t)gk * N + gc];
                else {
                    if (gc + 0 < N) v.x = Bw[(size_t)gk * N + gc + 0];
                    if (gc + 1 < N) v.y = Bw[(size_t)gk * N + gc + 1];
                    if (gc + 2 < N) v.z = Bw[(size_t)gk * N + gc + 2];
                    if (gc + 3 < N) v.w = Bw[(size_t)gk * N + gc + 3];
                }
            }
            *(float4*)&sB[r][c] = v;
        }
        __syncthreads();
        #pragma unroll
        for (int kk = 0; kk < 16; ++kk) {
            float a0 = sA[kk][ty * 2], a1 = sA[kk][ty * 2 + 1];
            float4 b = *(float4*)&sB[kk][tx * 4];
            acc[0][0] += a0 * b.x; acc[0][1] += a0 * b.y;
            acc[0][2] += a0 * b.z; acc[0][3] += a0 * b.w;
            acc[1][0] += a1 * b.x; acc[1][1] += a1 * b.y;
            acc[1][2] += a1 * b.z; acc[1][3] += a1 * b.w;
        }
        __syncthreads();
    }
    #pragma unroll
    for (int i = 0; i < 2; ++i) {
        int r = row0 + ty * 2 + i;
        if (r >= M) continue;
        #pragma unroll
        for (int j = 0; j < 4; ++j) {
            int c = col0 + tx * 4 + j;
            if (c >= N) continue;
            float v = acc[i][j] + bias[c];
            if (act) v = tanhf(v);
            C[(size_t)r * N + c] = v;
        }
    }
}

// ---------------- sort batches by length (descending) + reset barriers ----------------
__global__ void sort_perm_kernel(const int* __restrict__ h_lens)
{
    __shared__ int lens[BB];
    int i = threadIdx.x;
    lens[i] = h_lens[i];
    for (int e = i; e < G * 32; e += BB) {
        g_barx[e >> 5][e & 31] = 0u;
        g_gox[e >> 5][e & 31]  = 0u;
    }
    __syncthreads();
    int li = lens[i];
    int r = 0;
    for (int j = 0; j < BB; ++j) {
        int lj = lens[j];
        r += (lj > li) || (lj == li && j < i);
    }
    g_perm[r] = i;   // position r (0 = longest) holds original batch i
}

// ---------------- pack h0_stack transposed (permuted columns) ----------------
__global__ void pack_h0_kernel(const float* __restrict__ x)
{
    int idx = blockIdx.x * blockDim.x + threadIdx.x;
    const int total = HH * WHCOL;
    int stride = gridDim.x * blockDim.x;
    for (int i = idx; i < total; i += stride) {
        int k = i / WHCOL, p = i % WHCOL;   // column = sorted position
        int b = g_perm[p];
        g_hbuf[0][i] = (k < SS) ? x[b * SS + k] : g_h0[b * RNN_ + (k - SS)];
    }
}

// ---------------- persistent LSTM ----------------
struct LstmSmem {
    float Ws[HH * NCOL];             // 66560 B : [k][wid][q][t]  (t = jj within pair)
    float tile[2][KTILE * MB];       // 33280 B : double-buffered h tiles [kl][m]
    float Wi[CD1 * NCOL];            // 640
    float bs[NCOL];                  // 128
    float u[MB * CD1];               // 1280
    float dl[MB];                    // 256
    int   hl[MB];                    // 256
    int   pb[MB];                    // 256 : original batch index per column
    int   mx;                        // 4
};
static_assert(sizeof(LstmSmem) <= 116224, "smem over per-CTA budget for occ 2");

__global__ void __launch_bounds__(THREADS, 2)
lstm_kernel(const float* __restrict__ rnn_input, const float* __restrict__ deltas,
            const int* __restrict__ h_lens, const float* __restrict__ W_ih,
            const float* __restrict__ W_hh, const float* __restrict__ b_lstm)
{
    extern __shared__ char smem_raw[];
    LstmSmem& sm = *reinterpret_cast<LstmSmem*>(smem_raw);
    const int tid   = threadIdx.x;
    int grp, chunk;
    bid_map(blockIdx.x, grp, chunk);
    const int mb0   = grp * MB;      // column base in g_hbuf (sorted order)
    const int wid   = tid >> 5;      // warp id: covers jj = 2*wid, 2*wid+1
    const int lane  = tid & 31;
    const int jg0   = chunk * CHJ + wid * 2;   // global h index of t=0 (< 520)
    const int m0    = lane * 2;      // 2 batches per lane

    // ---- one-time loads: weight slice resident in SMEM ----
    // Ws layout: ((k*4 + w)*4 + q)*2 + t
    for (int i = tid; i < HH * NCOL; i += THREADS) {
        int t = i & 1, q = (i >> 1) & 3, w = (i >> 3) & 3, k = i >> 5;
        sm.Ws[i] = W_hh[(size_t)k * H4 + q * HH + chunk * CHJ + w * 2 + t];
    }
    for (int i = tid; i < CD1 * NCOL; i += THREADS) {
        int t = i & 1, q = (i >> 1) & 3, w = (i >> 3) & 3, c = i >> 5;
        sm.Wi[i] = W_ih[(size_t)c * H4 + q * HH + chunk * CHJ + w * 2 + t];
    }
    if (tid < NCOL) {
        int t = tid & 1, q = (tid >> 1) & 3, w = (tid >> 3) & 3;
        sm.bs[tid] = b_lstm[q * HH + chunk * CHJ + w * 2 + t];
    }
    if (tid < MB) {
        int ob = g_perm[mb0 + tid];
        sm.pb[tid] = ob;
        sm.hl[tid] = h_lens[ob];
    }
    __syncthreads();
    if (tid == 0) {
        int mx = 1;
        for (int m = 0; m < MB; ++m) mx = max(mx, sm.hl[m]);
        sm.mx = mx;
    }
    __syncthreads();
    const int maxlen = sm.mx;

    float creg[2][2] = {{0.f, 0.f}, {0.f, 0.f}};   // [t][i]
    float hreg[2][2];
    {
        float2 a = *(const float2*)&g_hbuf[0][(size_t)jg0 * WHCOL + mb0 + m0];
        float2 b = *(const float2*)&g_hbuf[0][(size_t)(jg0 + 1) * WHCOL + mb0 + m0];
        hreg[0][0] = a.x; hreg[0][1] = a.y;
        hreg[1][0] = b.x; hreg[1][1] = b.y;
    }

    uint32_t tile_s[2];
    tile_s[0] = (uint32_t)__cvta_generic_to_shared(&sm.tile[0][0]);
    tile_s[1] = (uint32_t)__cvta_generic_to_shared(&sm.tile[1][0]);
    const uint32_t ws_s = (uint32_t)__cvta_generic_to_shared(&sm.Ws[0]) + wid * 32;

    // prefetch step-0 inputs (u has 320 elems over 128 threads: 3 slots)
    float ureg[3] = {0.f, 0.f, 0.f};
    float dreg = 0.f;
    #pragma unroll
    for (int r = 0; r < 3; ++r) {
        int e = tid + r * THREADS;
        if (e < MB * CD1) {
            int m = e / CD1, c = e % CD1;
            ureg[r] = rnn_input[((size_t)sm.pb[m] * TT) * CD1 + c];
        }
    }
    if (tid < MB) dreg = deltas[(size_t)sm.pb[tid] * TT];

    for (int s = 0; s < maxlen; ++s) {
        #pragma unroll
        for (int r = 0; r < 3; ++r) {
            int e = tid + r * THREADS;
            if (e < MB * CD1) sm.u[e] = ureg[r];
        }
        if (tid < MB) sm.dl[tid] = dreg;

        const float* __restrict__ hsrc = g_hbuf[s & 1] + mb0;
        float* __restrict__ hdst = g_hbuf[(s & 1) ^ 1];

        // issue tile 0
        #pragma unroll
        for (int it = 0; it < 9; ++it) {
            int i = tid + it * THREADS;
            if (i < KTILE * (MB / 4)) {
                int kl = i >> 4, q4 = i & 15;
                cp16(tile_s[0] + (uint32_t)(kl * MB + q4 * 4) * 4,
                     hsrc + (size_t)kl * WHCOL + q4 * 4);
            }
        }
        asm volatile("cp.async.commit_group;");

        // accumulators: [q][i] packed over (j0,j1)
        unsigned long long ai0 = 0, af0 = 0, ag0 = 0, ao0 = 0;
        unsigned long long ai1 = 0, af1 = 0, ag1 = 0, ao1 = 0;

        #pragma unroll 1
        for (int p = 0; p < NPH; ++p) {
            asm volatile("cp.async.wait_group 0;");
            __syncthreads();                      // tile p visible; other buf free
            if (p < NPH - 1) {
                const float* src = hsrc + (size_t)(p + 1) * KTILE * WHCOL;
                uint32_t dst = tile_s[(p + 1) & 1];
                #pragma unroll
                for (int it = 0; it < 9; ++it) {
                    int i = tid + it * THREADS;
                    if (i < KTILE * (MB / 4)) {
                        int kl = i >> 4, q4 = i & 15;
                        cp16(dst + (uint32_t)(kl * MB + q4 * 4) * 4,
                             src + (size_t)kl * WHCOL + q4 * 4);
                    }
                }
                asm volatile("cp.async.commit_group;");
            }
            {
                uint32_t wb = ws_s + (uint32_t)(p * KTILE) * (NCOL * 4);
                uint32_t hb = tile_s[p & 1] + m0 * 4;
                #pragma unroll 5
                for (int kl = 0; kl < KTILE; ++kl) {
                    unsigned long long wi_, wf_, wg_, wo_;
                    asm("ld.shared.v2.u64 {%0, %1}, [%2];"
                        : "=l"(wi_), "=l"(wf_) : "r"(wb));
                    asm("ld.shared.v2.u64 {%0, %1}, [%2];"
                        : "=l"(wg_), "=l"(wo_) : "r"(wb + 16));
                    float h0, h1;
                    asm("ld.shared.v2.f32 {%0, %1}, [%2];"
                        : "=f"(h0), "=f"(h1) : "r"(hb));
                    unsigned long long p0 = splat2(h0), p1 = splat2(h1);
                    FMA2(ai0, wi_, p0); FMA2(af0, wf_, p0);
                    FMA2(ag0, wg_, p0); FMA2(ao0, wo_, p0);
                    FMA2(ai1, wi_, p1); FMA2(af1, wf_, p1);
                    FMA2(ag1, wg_, p1); FMA2(ao1, wo_, p1);
                    wb += NCOL * 4;
                    hb += MB * 4;
                }
            }
        }

        // ---- epilogue: gates, activations, state update, last capture ----
        {
            float zi[2][2], zf[2][2], zg[2][2], zo[2][2];   // [t][i]
            unpk2(ai0, zi[0][0], zi[1][0]); unpk2(ai1, zi[0][1], zi[1][1]);
            unpk2(af0, zf[0][0], zf[1][0]); unpk2(af1, zf[0][1], zf[1][1]);
            unpk2(ag0, zg[0][0], zg[1][0]); unpk2(ag1, zg[0][1], zg[1][1]);
            unpk2(ao0, zo[0][0], zo[1][0]); unpk2(ao1, zo[0][1], zo[1][1]);
            #pragma unroll
            for (int t = 0; t < 2; ++t) {
                float b0 = sm.bs[(wid * 4 + 0) * 2 + t];
                float b1 = sm.bs[(wid * 4 + 1) * 2 + t];
                float b2 = sm.bs[(wid * 4 + 2) * 2 + t];
                float b3 = sm.bs[(wid * 4 + 3) * 2 + t];
                #pragma unroll
                for (int i = 0; i < 2; ++i) {
                    int m = m0 + i;
                    float vi = zi[t][i] + b0, vf = zf[t][i] + b1;
                    float vg = zg[t][i] + b2, vo = zo[t][i] + b3;
                    #pragma unroll
                    for (int c = 0; c < CD1; ++c) {
                        float uv = sm.u[m * CD1 + c];
                        const float* wr = &sm.Wi[(c * 4 + wid) * 8];
                        vi += uv * wr[0 + t]; vf += uv * wr[2 + t];
                        vg += uv * wr[4 + t]; vo += uv * wr[6 + t];
                    }
                    float cn = fsig(vf) * creg[t][i] + fsig(vi) * ftanh_(vg);
                    float hn = fsig(vo) * ftanh_(cn);
                    int len = sm.hl[m];
                    if (s < len) {
                        if (s == len - 1) {
                            float d = sm.dl[m];
                            g_last[(size_t)sm.pb[m] * HH + jg0 + t] =
                                (1.f - d) * hreg[t][i] + d * hn;
                        }
                        creg[t][i] = cn;
                        hreg[t][i] = hn;
                    }
                }
                float2 v = make_float2(hreg[t][0], hreg[t][1]);
                __stcg((float2*)&hdst[(size_t)(jg0 + t) * WHCOL + mb0 + m0], v);
            }
        }

        // prefetch next-step inputs (overlaps barrier wait)
        if (s + 1 < TT) {
            #pragma unroll
            for (int r = 0; r < 3; ++r) {
                int e = tid + r * THREADS;
                if (e < MB * CD1) {
                    int m = e / CD1, c = e % CD1;
                    ureg[r] = rnn_input[((size_t)sm.pb[m] * TT + s + 1) * CD1 + c];
                }
            }
            if (tid < MB) dreg = deltas[(size_t)sm.pb[tid] * TT + s + 1];
        }

        // ---- per-group barrier: padded counter + master/go broadcast ----
        // Arrival stays the proven strong pattern: all-thread release fence,
        // then strong atomicAdd. Master (chunk 0) alone polls the counter;
        // others poll the per-group padded go word it publishes (atomicExch).
        __threadfence();        // release: every storing thread fences its own STGs
        __syncthreads();
        if (tid == 0) {
            const unsigned int tgt = (unsigned int)(s + 1);
            atomicAdd(&g_barx[grp][0], 1u);
            if (chunk == 0) {
                while (*(volatile unsigned int*)&g_barx[grp][0] < tgt * NCH) { }
                __threadfence();                      // acquire arrivals / release go
                atomicExch(&g_gox[grp][0], tgt);
            } else {
                while (*(volatile unsigned int*)&g_gox[grp][0] < tgt) { }
                __threadfence();                      // acquire
            }
        }
        __syncthreads();
    }
}

// ---------------- launch ----------------
extern "C" void kernel_launch(void* const* d_in, const int* in_sizes, int n_in,
                              void* d_out, int out_size)
{
    (void)in_sizes; (void)n_in; (void)out_size;
    const float* x        = (const float*)d_in[0];
    const float* rnn_in   = (const float*)d_in[1];
    const float* deltas   = (const float*)d_in[2];
    const int*   h_lens   = (const int*)d_in[3];
    const float* enc_w1   = (const float*)d_in[4];
    const float* enc_b1   = (const float*)d_in[5];
    const float* enc_w2   = (const float*)d_in[6];
    const float* enc_b2   = (const float*)d_in[7];
    const float* enc_w3   = (const float*)d_in[8];
    const float* enc_b3   = (const float*)d_in[9];
    const float* W_ih     = (const float*)d_in[10];
    const float* W_hh     = (const float*)d_in[11];
    const float* b_lstm   = (const float*)d_in[12];
    const float* dec_w1   = (const float*)d_in[13];
    const float* dec_b1   = (const float*)d_in[14];
    const float* dec_w2   = (const float*)d_in[15];
    const float* dec_b2   = (const float*)d_in[16];
    const float* dec_w3   = (const float*)d_in[17];
    const float* dec_b3   = (const float*)d_in[18];
    float* out = (float*)d_out;

    float *t1, *t2, *h0, *last, *z1, *z2;
    cudaGetSymbolAddress((void**)&t1,   g_t1);
    cudaGetSymbolAddress((void**)&t2,   g_t2);
    cudaGetSymbolAddress((void**)&h0,   g_h0);
    cudaGetSymbolAddress((void**)&last, g_last);
    cudaGetSymbolAddress((void**)&z1,   g_z1);
    cudaGetSymbolAddress((void**)&z2,   g_z2);

    // sort batches by length (also resets barrier counters/go words)
    sort_perm_kernel<<<1, BB>>>(h_lens);

    // encoder (32x64 tiles: 8 row-blocks of 32)
    gemm_bias_act<<<dim3(EE / 64, 8), 256>>>(x,  enc_w1, enc_b1, t1, BB, EE,  SS,  1);
    gemm_bias_act<<<dim3(EE / 64, 8), 256>>>(t1, enc_w2, enc_b2, t2, BB, EE,  EE,  1);
    gemm_bias_act<<<dim3(RNN_ / 64, 8), 256>>>(t2, enc_w3, enc_b3, h0, BB, RNN_, EE, 0);

    // pack transposed h0_stack (sorted column order)
    pack_h0_kernel<<<120, 256>>>(x);

    // persistent LSTM (260 CTAs x 128 threads, occupancy 2 -> all resident)
    cudaFuncSetAttribute(lstm_kernel, cudaFuncAttributeMaxDynamicSharedMemorySize,
                         (int)sizeof(LstmSmem));
    lstm_kernel<<<G * NCH, THREADS, sizeof(LstmSmem)>>>(
        rnn_in, deltas, h_lens, W_ih, W_hh, b_lstm);

    // decoder
    gemm_bias_act<<<dim3((DD + 63) / 64, 8), 256>>>(last, dec_w1, dec_b1, z1, BB, DD, HH, 1);
    gemm_bias_act<<<dim3((DD + 63) / 64, 8), 256>>>(z1,   dec_w2, dec_b2, z2, BB, DD, DD, 1);
    gemm_bias_act<<<dim3(1, 8), 256>>>(z2, dec_w3, dec_b3, out, BB, SS, DD, 0);
}

// round 17
// speedup vs baseline: 1.0455x; 1.0455x over previous
#include <cuda_runtime.h>
#include <math.h>
#include <stdint.h>

// ---------------- problem constants ----------------
#define BB    256
#define TT    512
#define SS    8
#define CD1   5        // CD+1
#define RNN_  512
#define HH    520      // RNN + S
#define H4    2080
#define EE    1024
#define DD    1040

// ---------------- LSTM partitioning (exact, no padding) ----------------
#define G       4      // batch groups, 64 sorted batches each
#define MB      64     // batches per group
#define WHCOL   256    // width of transposed h buffer (= BB)
#define NCH     65     // h-chunks (CTAs per group); 65*8 = 520 exactly
#define CHJ     8      // h indices per chunk (4 warps x 2 jj)
#define NCOL    32     // 4*CHJ gate columns per CTA
#define KTILE   65     // K tile rows; 8 phases cover 520
#define NPH     8
#define THREADS 128    // 4 warps

// ---------------- scratch (static __device__, no allocation) ----------------
__device__ __align__(16) float g_t1[BB * EE];
__device__ __align__(16) float g_t2[BB * EE];
__device__ __align__(16) float g_h0[BB * RNN_];
__device__ __align__(16) float g_hbuf[2][HH * WHCOL];
__device__ __align__(16) float g_last[BB * HH];
__device__ __align__(16) float g_z1[BB * DD];
__device__ __align__(16) float g_z2[BB * DD];
__device__ int g_perm[BB];
__device__ unsigned int g_bar[8];

// ---------------- helpers ----------------
__device__ __forceinline__ float fsig(float x) {
    return 1.f / (1.f + __expf(-x));
}
__device__ __forceinline__ float ftanh_(float x) {
    float ax = fabsf(x);
    float e = __expf(-2.f * ax);
    float r = (1.f - e) / (1.f + e);
    return x < 0.f ? -r : r;
}
__device__ __forceinline__ unsigned long long splat2(float w) {
    unsigned long long r;
    asm("mov.b64 %0, {%1, %1};" : "=l"(r) : "f"(w));
    return r;
}
__device__ __forceinline__ void unpk2(unsigned long long v, float& lo, float& hi) {
    asm("mov.b64 {%0, %1}, %2;" : "=f"(lo), "=f"(hi) : "l"(v));
}
#define FMA2(d, a, b) asm("fma.rn.f32x2 %0, %1, %2, %0;" : "+l"(d) : "l"(a), "l"(b))

__device__ __forceinline__ void cp16(uint32_t saddr, const void* gaddr) {
    asm volatile("cp.async.cg.shared.global [%0], [%1], 16;"
                 :: "r"(saddr), "l"(gaddr));
}
// predicated cp.async with zero-fill (src-size 0 reads nothing)
__device__ __forceinline__ void cpa4(uint32_t saddr, const void* gaddr, uint32_t ss) {
    asm volatile("cp.async.ca.shared.global [%0], [%1], 4, %2;"
                 :: "r"(saddr), "l"(gaddr), "r"(ss));
}
__device__ __forceinline__ void cpa16(uint32_t saddr, const void* gaddr, uint32_t ss) {
    asm volatile("cp.async.cg.shared.global [%0], [%1], 16, %2;"
                 :: "r"(saddr), "l"(gaddr), "r"(ss));
}
template <int NW>
__device__ __forceinline__ void cp_wait_group() {
    asm volatile("cp.async.wait_group %0;" :: "n"(NW) : "memory");
}

// ---------------- GEMM: C = act(A[MxK] @ B[KxN] + bias) ----------------
// 32x64 tile, 256 threads, cp.async double-buffered K-stages of 16.
// Same tile shape / compute / epilogue as the R10-proven kernel; only the
// load path changed (async pipelined, zero-fill guards). Requires M == 256
// (all call sites) and N % 4 == 0 (all call sites: 1024, 512, 1040, 8).
__global__ void gemm_bias_act(const float* __restrict__ A, const float* __restrict__ Bw,
                              const float* __restrict__ bias, float* __restrict__ C,
                              int M, int N, int K, int act)
{
    __shared__ float sA[2][16][36];   // [buf][k][m]
    __shared__ float sB[2][16][68];   // [buf][k][n]
    int tid = threadIdx.x;            // 256
    int row0 = blockIdx.y * 32, col0 = blockIdx.x * 64;
    int tx = tid & 15, ty = tid >> 4;
    float acc[2][4] = {{0.f, 0.f, 0.f, 0.f}, {0.f, 0.f, 0.f, 0.f}};

    uint32_t sa_s[2], sb_s[2];
    sa_s[0] = (uint32_t)__cvta_generic_to_shared(&sA[0][0][0]);
    sa_s[1] = (uint32_t)__cvta_generic_to_shared(&sA[1][0][0]);
    sb_s[0] = (uint32_t)__cvta_generic_to_shared(&sB[0][0][0]);
    sb_s[1] = (uint32_t)__cvta_generic_to_shared(&sB[1][0][0]);

    const int nk = (K + 15) / 16;

    // issue one K-stage into buffer `buf`
    auto issue = [&](int kt, int buf) {
        int k0 = kt * 16;
        // A: 32 rows x 16 k = 512 scalars, 2 per thread
        #pragma unroll
        for (int e = 0; e < 2; ++e) {
            int idx = tid + e * 256;
            int m = idx >> 4, kk = idx & 15;
            int gk = k0 + kk;
            bool v = (gk < K);                       // rows always valid (M=256)
            const float* src = v ? &A[(size_t)(row0 + m) * K + gk] : A;
            cpa4(sa_s[buf] + (uint32_t)(kk * 36 + m) * 4, src, v ? 4u : 0u);
        }
        // B: 16 k-rows x 64 cols, one float4 per thread
        {
            int r = tid >> 4, c = (tid & 15) * 4;
            int gk = k0 + r, gc = col0 + c;
            bool v = (gk < K) && (gc < N);           // N % 4 == 0 -> all-or-nothing
            const float* src = v ? &Bw[(size_t)gk * N + gc] : Bw;
            cpa16(sb_s[buf] + (uint32_t)(r * 68 + c) * 4, src, v ? 16u : 0u);
        }
        asm volatile("cp.async.commit_group;");
    };

    issue(0, 0);
    for (int kt = 0; kt < nk; ++kt) {
        int buf = kt & 1;
        if (kt + 1 < nk) {
            issue(kt + 1, buf ^ 1);
            cp_wait_group<1>();          // stage kt done; kt+1 may be in flight
        } else {
            cp_wait_group<0>();
        }
        __syncthreads();
        #pragma unroll
        for (int kk = 0; kk < 16; ++kk) {
            float a0 = sA[buf][kk][ty * 2], a1 = sA[buf][kk][ty * 2 + 1];
            float4 b = *(float4*)&sB[buf][kk][tx * 4];
            acc[0][0] += a0 * b.x; acc[0][1] += a0 * b.y;
            acc[0][2] += a0 * b.z; acc[0][3] += a0 * b.w;
            acc[1][0] += a1 * b.x; acc[1][1] += a1 * b.y;
            acc[1][2] += a1 * b.z; acc[1][3] += a1 * b.w;
        }
        __syncthreads();                 // buffer free before stage kt+2 writes it
    }

    #pragma unroll
    for (int i = 0; i < 2; ++i) {
        int r = row0 + ty * 2 + i;
        if (r >= M) continue;
        #pragma unroll
        for (int j = 0; j < 4; ++j) {
            int c = col0 + tx * 4 + j;
            if (c >= N) continue;
            float v = acc[i][j] + bias[c];
            if (act) v = tanhf(v);
            C[(size_t)r * N + c] = v;
        }
    }
}

// ---------------- sort batches by length (descending) + reset barriers ----------------
__global__ void sort_perm_kernel(const int* __restrict__ h_lens)
{
    __shared__ int lens[BB];
    int i = threadIdx.x;
    lens[i] = h_lens[i];
    if (i < 8) g_bar[i] = 0u;
    __syncthreads();
    int li = lens[i];
    int r = 0;
    for (int j = 0; j < BB; ++j) {
        int lj = lens[j];
        r += (lj > li) || (lj == li && j < i);
    }
    g_perm[r] = i;   // position r (0 = longest) holds original batch i
}

// ---------------- pack h0_stack transposed (permuted columns) ----------------
__global__ void pack_h0_kernel(const float* __restrict__ x)
{
    int idx = blockIdx.x * blockDim.x + threadIdx.x;
    const int total = HH * WHCOL;
    int stride = gridDim.x * blockDim.x;
    for (int i = idx; i < total; i += stride) {
        int k = i / WHCOL, p = i % WHCOL;   // column = sorted position
        int b = g_perm[p];
        g_hbuf[0][i] = (k < SS) ? x[b * SS + k] : g_h0[b * RNN_ + (k - SS)];
    }
}

// ---------------- persistent LSTM (R10-proven, byte-identical) ----------------
struct LstmSmem {
    float Ws[HH * NCOL];             // 66560 B : [k][wid][q][t]  (t = jj within pair)
    float tile[2][KTILE * MB];       // 33280 B : double-buffered h tiles [kl][m]
    float Wi[CD1 * NCOL];
    float bs[NCOL];
    float u[MB * CD1];
    float dl[MB];
    int   hl[MB];
    int   pb[MB];
    int   mx;
};
static_assert(sizeof(LstmSmem) <= 116224, "smem over per-CTA budget for occ 2");

__global__ void __launch_bounds__(THREADS, 2)
lstm_kernel(const float* __restrict__ rnn_input, const float* __restrict__ deltas,
            const int* __restrict__ h_lens, const float* __restrict__ W_ih,
            const float* __restrict__ W_hh, const float* __restrict__ b_lstm)
{
    extern __shared__ char smem_raw[];
    LstmSmem& sm = *reinterpret_cast<LstmSmem*>(smem_raw);
    const int tid   = threadIdx.x;
    const int grp   = blockIdx.x / NCH;
    const int chunk = blockIdx.x % NCH;
    const int mb0   = grp * MB;      // column base in g_hbuf (sorted order)
    const int wid   = tid >> 5;      // warp id: covers jj = 2*wid, 2*wid+1
    const int lane  = tid & 31;
    const int jg0   = chunk * CHJ + wid * 2;   // global h index of t=0 (< 520)
    const int m0    = lane * 2;      // 2 batches per lane

    // ---- one-time loads: weight slice resident in SMEM ----
    // Ws layout: ((k*4 + w)*4 + q)*2 + t
    for (int i = tid; i < HH * NCOL; i += THREADS) {
        int t = i & 1, q = (i >> 1) & 3, w = (i >> 3) & 3, k = i >> 5;
        sm.Ws[i] = W_hh[(size_t)k * H4 + q * HH + chunk * CHJ + w * 2 + t];
    }
    for (int i = tid; i < CD1 * NCOL; i += THREADS) {
        int t = i & 1, q = (i >> 1) & 3, w = (i >> 3) & 3, c = i >> 5;
        sm.Wi[i] = W_ih[(size_t)c * H4 + q * HH + chunk * CHJ + w * 2 + t];
    }
    if (tid < NCOL) {
        int t = tid & 1, q = (tid >> 1) & 3, w = (tid >> 3) & 3;
        sm.bs[tid] = b_lstm[q * HH + chunk * CHJ + w * 2 + t];
    }
    if (tid < MB) {
        int ob = g_perm[mb0 + tid];
        sm.pb[tid] = ob;
        sm.hl[tid] = h_lens[ob];
    }
    __syncthreads();
    if (tid == 0) {
        int mx = 1;
        for (int m = 0; m < MB; ++m) mx = max(mx, sm.hl[m]);
        sm.mx = mx;
    }
    __syncthreads();
    const int maxlen = sm.mx;

    float creg[2][2] = {{0.f, 0.f}, {0.f, 0.f}};   // [t][i]
    float hreg[2][2];
    {
        float2 a = *(const float2*)&g_hbuf[0][(size_t)jg0 * WHCOL + mb0 + m0];
        float2 b = *(const float2*)&g_hbuf[0][(size_t)(jg0 + 1) * WHCOL + mb0 + m0];
        hreg[0][0] = a.x; hreg[0][1] = a.y;
        hreg[1][0] = b.x; hreg[1][1] = b.y;
    }

    uint32_t tile_s[2];
    tile_s[0] = (uint32_t)__cvta_generic_to_shared(&sm.tile[0][0]);
    tile_s[1] = (uint32_t)__cvta_generic_to_shared(&sm.tile[1][0]);
    const uint32_t ws_s = (uint32_t)__cvta_generic_to_shared(&sm.Ws[0]) + wid * 32;

    // prefetch step-0 inputs (u has 320 elems over 128 threads: 3 slots)
    float ureg[3] = {0.f, 0.f, 0.f};
    float dreg = 0.f;
    #pragma unroll
    for (int r = 0; r < 3; ++r) {
        int e = tid + r * THREADS;
        if (e < MB * CD1) {
            int m = e / CD1, c = e % CD1;
            ureg[r] = rnn_input[((size_t)sm.pb[m] * TT) * CD1 + c];
        }
    }
    if (tid < MB) dreg = deltas[(size_t)sm.pb[tid] * TT];

    for (int s = 0; s < maxlen; ++s) {
        #pragma unroll
        for (int r = 0; r < 3; ++r) {
            int e = tid + r * THREADS;
            if (e < MB * CD1) sm.u[e] = ureg[r];
        }
        if (tid < MB) sm.dl[tid] = dreg;

        const float* __restrict__ hsrc = g_hbuf[s & 1] + mb0;
        float* __restrict__ hdst = g_hbuf[(s & 1) ^ 1];

        // issue tile 0
        #pragma unroll
        for (int it = 0; it < 9; ++it) {
            int i = tid + it * THREADS;
            if (i < KTILE * (MB / 4)) {
                int kl = i >> 4, q4 = i & 15;
                cp16(tile_s[0] + (uint32_t)(kl * MB + q4 * 4) * 4,
                     hsrc + (size_t)kl * WHCOL + q4 * 4);
            }
        }
        asm volatile("cp.async.commit_group;");

        // accumulators: [q][i] packed over (j0,j1)
        unsigned long long ai0 = 0, af0 = 0, ag0 = 0, ao0 = 0;
        unsigned long long ai1 = 0, af1 = 0, ag1 = 0, ao1 = 0;

        #pragma unroll 1
        for (int p = 0; p < NPH; ++p) {
            asm volatile("cp.async.wait_group 0;");
            __syncthreads();                      // tile p visible; other buf free
            if (p < NPH - 1) {
                const float* src = hsrc + (size_t)(p + 1) * KTILE * WHCOL;
                uint32_t dst = tile_s[(p + 1) & 1];
                #pragma unroll
                for (int it = 0; it < 9; ++it) {
                    int i = tid + it * THREADS;
                    if (i < KTILE * (MB / 4)) {
                        int kl = i >> 4, q4 = i & 15;
                        cp16(dst + (uint32_t)(kl * MB + q4 * 4) * 4,
                             src + (size_t)kl * WHCOL + q4 * 4);
                    }
                }
                asm volatile("cp.async.commit_group;");
            }
            {
                uint32_t wb = ws_s + (uint32_t)(p * KTILE) * (NCOL * 4);
                uint32_t hb = tile_s[p & 1] + m0 * 4;
                #pragma unroll 5
                for (int kl = 0; kl < KTILE; ++kl) {
                    unsigned long long wi_, wf_, wg_, wo_;
                    asm("ld.shared.v2.u64 {%0, %1}, [%2];"
                        : "=l"(wi_), "=l"(wf_) : "r"(wb));
                    asm("ld.shared.v2.u64 {%0, %1}, [%2];"
                        : "=l"(wg_), "=l"(wo_) : "r"(wb + 16));
                    float h0, h1;
                    asm("ld.shared.v2.f32 {%0, %1}, [%2];"
                        : "=f"(h0), "=f"(h1) : "r"(hb));
                    unsigned long long p0 = splat2(h0), p1 = splat2(h1);
                    FMA2(ai0, wi_, p0); FMA2(af0, wf_, p0);
                    FMA2(ag0, wg_, p0); FMA2(ao0, wo_, p0);
                    FMA2(ai1, wi_, p1); FMA2(af1, wf_, p1);
                    FMA2(ag1, wg_, p1); FMA2(ao1, wo_, p1);
                    wb += NCOL * 4;
                    hb += MB * 4;
                }
            }
        }

        // ---- epilogue: gates, activations, state update, last capture ----
        {
            float zi[2][2], zf[2][2], zg[2][2], zo[2][2];   // [t][i]
            unpk2(ai0, zi[0][0], zi[1][0]); unpk2(ai1, zi[0][1], zi[1][1]);
            unpk2(af0, zf[0][0], zf[1][0]); unpk2(af1, zf[0][1], zf[1][1]);
            unpk2(ag0, zg[0][0], zg[1][0]); unpk2(ag1, zg[0][1], zg[1][1]);
            unpk2(ao0, zo[0][0], zo[1][0]); unpk2(ao1, zo[0][1], zo[1][1]);
            #pragma unroll
            for (int t = 0; t < 2; ++t) {
                float b0 = sm.bs[(wid * 4 + 0) * 2 + t];
                float b1 = sm.bs[(wid * 4 + 1) * 2 + t];
                float b2 = sm.bs[(wid * 4 + 2) * 2 + t];
                float b3 = sm.bs[(wid * 4 + 3) * 2 + t];
                #pragma unroll
                for (int i = 0; i < 2; ++i) {
                    int m = m0 + i;
                    float vi = zi[t][i] + b0, vf = zf[t][i] + b1;
                    float vg = zg[t][i] + b2, vo = zo[t][i] + b3;
                    #pragma unroll
                    for (int c = 0; c < CD1; ++c) {
                        float uv = sm.u[m * CD1 + c];
                        const float* wr = &sm.Wi[(c * 4 + wid) * 8];
                        vi += uv * wr[0 + t]; vf += uv * wr[2 + t];
                        vg += uv * wr[4 + t]; vo += uv * wr[6 + t];
                    }
                    float cn = fsig(vf) * creg[t][i] + fsig(vi) * ftanh_(vg);
                    float hn = fsig(vo) * ftanh_(cn);
                    int len = sm.hl[m];
                    if (s < len) {
                        if (s == len - 1) {
                            float d = sm.dl[m];
                            g_last[(size_t)sm.pb[m] * HH + jg0 + t] =
                                (1.f - d) * hreg[t][i] + d * hn;
                        }
                        creg[t][i] = cn;
                        hreg[t][i] = hn;
                    }
                }
                float2 v = make_float2(hreg[t][0], hreg[t][1]);
                __stcg((float2*)&hdst[(size_t)(jg0 + t) * WHCOL + mb0 + m0], v);
            }
        }

        // prefetch next-step inputs (overlaps barrier wait)
        if (s + 1 < TT) {
            #pragma unroll
            for (int r = 0; r < 3; ++r) {
                int e = tid + r * THREADS;
                if (e < MB * CD1) {
                    int m = e / CD1, c = e % CD1;
                    ureg[r] = rnn_input[((size_t)sm.pb[m] * TT + s + 1) * CD1 + c];
                }
            }
            if (tid < MB) dreg = deltas[(size_t)sm.pb[tid] * TT + s + 1];
        }

        // ---- per-group global barrier (proven: strong atomic + volatile poll) ----
        __threadfence();        // release: every storing thread fences its own STGs
        __syncthreads();
        if (tid == 0) {
            atomicAdd(&g_bar[grp], 1u);
            unsigned int target = (unsigned int)(s + 1) * NCH;
            while (*(volatile unsigned int*)&g_bar[grp] < target) { }
            __threadfence();    // acquire
        }
        __syncthreads();
    }
}

// ---------------- launch ----------------
extern "C" void kernel_launch(void* const* d_in, const int* in_sizes, int n_in,
                              void* d_out, int out_size)
{
    (void)in_sizes; (void)n_in; (void)out_size;
    const float* x        = (const float*)d_in[0];
    const float* rnn_in   = (const float*)d_in[1];
    const float* deltas   = (const float*)d_in[2];
    const int*   h_lens   = (const int*)d_in[3];
    const float* enc_w1   = (const float*)d_in[4];
    const float* enc_b1   = (const float*)d_in[5];
    const float* enc_w2   = (const float*)d_in[6];
    const float* enc_b2   = (const float*)d_in[7];
    const float* enc_w3   = (const float*)d_in[8];
    const float* enc_b3   = (const float*)d_in[9];
    const float* W_ih     = (const float*)d_in[10];
    const float* W_hh     = (const float*)d_in[11];
    const float* b_lstm   = (const float*)d_in[12];
    const float* dec_w1   = (const float*)d_in[13];
    const float* dec_b1   = (const float*)d_in[14];
    const float* dec_w2   = (const float*)d_in[15];
    const float* dec_b2   = (const float*)d_in[16];
    const float* dec_w3   = (const float*)d_in[17];
    const float* dec_b3   = (const float*)d_in[18];
    float* out = (float*)d_out;

    float *t1, *t2, *h0, *last, *z1, *z2;
    cudaGetSymbolAddress((void**)&t1,   g_t1);
    cudaGetSymbolAddress((void**)&t2,   g_t2);
    cudaGetSymbolAddress((void**)&h0,   g_h0);
    cudaGetSymbolAddress((void**)&last, g_last);
    cudaGetSymbolAddress((void**)&z1,   g_z1);
    cudaGetSymbolAddress((void**)&z2,   g_z2);

    // sort batches by length (also resets barrier counters)
    sort_perm_kernel<<<1, BB>>>(h_lens);

    // encoder (pipelined 32x64 tiles: 8 row-blocks of 32)
    gemm_bias_act<<<dim3(EE / 64, 8), 256>>>(x,  enc_w1, enc_b1, t1, BB, EE,  SS,  1);
    gemm_bias_act<<<dim3(EE / 64, 8), 256>>>(t1, enc_w2, enc_b2, t2, BB, EE,  EE,  1);
    gemm_bias_act<<<dim3(RNN_ / 64, 8), 256>>>(t2, enc_w3, enc_b3, h0, BB, RNN_, EE, 0);

    // pack transposed h0_stack (sorted column order)
    pack_h0_kernel<<<120, 256>>>(x);

    // persistent LSTM (260 CTAs x 128 threads, occupancy 2 -> all resident)
    cudaFuncSetAttribute(lstm_kernel, cudaFuncAttributeMaxDynamicSharedMemorySize,
                         (int)sizeof(LstmSmem));
    lstm_kernel<<<G * NCH, THREADS, sizeof(LstmSmem)>>>(
        rnn_in, deltas, h_lens, W_ih, W_hh, b_lstm);

    // decoder
    gemm_bias_act<<<dim3((DD + 63) / 64, 8), 256>>>(last, dec_w1, dec_b1, z1, BB, DD, HH, 1);
    gemm_bias_act<<<dim3((DD + 63) / 64, 8), 256>>>(z1,   dec_w2, dec_b2, z2, BB, DD, DD, 1);
    gemm_bias_act<<<dim3(1, 8), 256>>>(z2, dec_w3, dec_b3, out, BB, SS, DD, 0);
}